// round 3
// baseline (speedup 1.0000x reference)
#include <cuda_runtime.h>
#include <cstdint>

// ---------------- constants ----------------
#define Bn 32
#define Mn 448
#define Cn 384
#define Sn 512
#define SDn 128
#define Kn 8
#define NROWS (Bn * Sn)   // 16384

// ---------------- scratch ----------------
__device__ int      g_idx[NROWS * Kn];
__device__ float    g_X[NROWS * 128];        // [row][0:64]=h1(relu), [64:128]=agg1
__device__ unsigned g_proxy[Bn * SDn];       // encoded float max
__device__ float    g_kv[Bn * Cn];
__device__ float    g_vh[Bn * Cn];
__device__ float    g_g2qc[Bn * 1408];       // [0:1024]=g2, [1024:1408]=qc
__device__ float    g_g1[Bn * 1024];
__device__ float    g_partial[Bn * 11 * Cn];

// ---------------- helpers ----------------
__device__ __forceinline__ unsigned fenc(float f) {
    unsigned u = __float_as_uint(f);
    return (u & 0x80000000u) ? ~u : (u | 0x80000000u);
}
__device__ __forceinline__ float fdec(unsigned e) {
    unsigned u = (e & 0x80000000u) ? (e ^ 0x80000000u) : ~e;
    return __uint_as_float(u);
}

// ================= K0: fused knn + gc1 =================
// grid (Bn, 4): 128 points per block, 4 lanes per point. block 512.
__global__ __launch_bounds__(512) void knn_gc1_kernel(const float* __restrict__ skel,
                                                      const float* __restrict__ wroot,
                                                      const float* __restrict__ wrel,
                                                      const float* __restrict__ bias) {
    __shared__ float sx[Sn], sy[Sn], sz[Sn];
    __shared__ float cd[128 * 32];
    __shared__ int   ci[128 * 32];
    __shared__ float wgt[448];
    int b = blockIdx.x;
    int t = threadIdx.x;
    const float* sk = skel + (size_t)b * Sn * 3;

    // coalesced position load
    #pragma unroll
    for (int q = t; q < Sn * 3; q += 512) {
        float v = sk[q];
        int idx = q / 3, r = q - idx * 3;
        if (r == 0) sx[idx] = v; else if (r == 1) sy[idx] = v; else sz[idx] = v;
    }
    if (blockIdx.y == 0 && t < SDn) g_proxy[b * SDn + t] = 0u;
    if (t < 448) wgt[t] = (t < 192) ? wroot[t] : ((t < 384) ? wrel[t - 192] : bias[t - 384]);
    __syncthreads();

    int p = t >> 2, s4 = t & 3;
    int i = blockIdx.y * 128 + p;      // point index within batch
    float xi = sx[i], yi = sy[i], zi = sz[i];

    float bd[8]; int bi8[8];
    #pragma unroll
    for (int k = 0; k < 8; k++) { bd[k] = 3.0e38f; bi8[k] = 0; }

    // phase 1: each lane scans 128 candidates (j = jj*4 + s4), keeps sorted top-8
    for (int jj = 0; jj < 128; jj++) {
        int j = jj * 4 + s4;
        float dx = xi - sx[j], dy = yi - sy[j], dz = zi - sz[j];
        float d = fmaf(dx, dx, fmaf(dy, dy, dz * dz));
        if (j == i) d = 3.0e38f;
        if (d < bd[7]) {
            bd[7] = d; bi8[7] = j;
            #pragma unroll
            for (int k = 7; k > 0; k--) {
                if (bd[k] < bd[k - 1]) {
                    float td = bd[k]; bd[k] = bd[k - 1]; bd[k - 1] = td;
                    int ti = bi8[k]; bi8[k] = bi8[k - 1]; bi8[k - 1] = ti;
                }
            }
        }
    }
    #pragma unroll
    for (int k = 0; k < 8; k++) { cd[p * 32 + s4 * 8 + k] = bd[k]; ci[p * 32 + s4 * 8 + k] = bi8[k]; }
    __syncthreads();

    // phase 2: threads 0..127 merge 4 sorted lists -> final top-8, then gc1
    if (t < 128) {
        float fd[8]; int fi[8];
        #pragma unroll
        for (int k = 0; k < 8; k++) { fd[k] = 3.0e38f; fi[k] = 0; }
        for (int s = 0; s < 4; s++) {
            #pragma unroll
            for (int k = 0; k < 8; k++) {
                float d = cd[t * 32 + s * 8 + k];
                if (d >= fd[7]) break;          // source list sorted ascending
                int j = ci[t * 32 + s * 8 + k];
                fd[7] = d; fi[7] = j;
                #pragma unroll
                for (int m = 7; m > 0; m--) {
                    if (fd[m] < fd[m - 1]) {
                        float td = fd[m]; fd[m] = fd[m - 1]; fd[m - 1] = td;
                        int ti = fi[m]; fi[m] = fi[m - 1]; fi[m - 1] = ti;
                    }
                }
            }
        }
        int ip = blockIdx.y * 128 + t;
        int row = b * Sn + ip;
        float a0 = 0.f, a1 = 0.f, a2 = 0.f;
        #pragma unroll
        for (int k = 0; k < 8; k++) {
            int j = fi[k];
            g_idx[row * Kn + k] = j;
            a0 += sx[j]; a1 += sy[j]; a2 += sz[j];
        }
        float x0 = sx[ip], x1 = sy[ip], x2 = sz[ip];
        float* cif = (float*)ci;
        #pragma unroll
        for (int ch = 0; ch < 64; ch++) {
            float h = wgt[384 + ch];
            h = fmaf(x0, wgt[0 * 64 + ch], h);
            h = fmaf(x1, wgt[1 * 64 + ch], h);
            h = fmaf(x2, wgt[2 * 64 + ch], h);
            h = fmaf(a0, wgt[192 + 0 * 64 + ch], h);
            h = fmaf(a1, wgt[192 + 1 * 64 + ch], h);
            h = fmaf(a2, wgt[192 + 2 * 64 + ch], h);
            h = fmaxf(h, 0.f);
            if (ch < 32) cd[t * 32 + ch] = h; else cif[t * 32 + ch - 32] = h;
        }
    }
    __syncthreads();

    // cooperative coalesced store of h1 (128 points x 64 ch)
    float* cif = (float*)ci;
    #pragma unroll
    for (int q = t; q < 128 * 64; q += 512) {
        int p2 = q >> 6, ch = q & 63;
        float v = (ch < 32) ? cd[p2 * 32 + ch] : cif[p2 * 32 + ch - 32];
        g_X[(size_t)(b * Sn + blockIdx.y * 128 + p2) * 128 + ch] = v;
    }
}

// ================= K1: neighbor aggregation of h1 =================
__global__ void agg_kernel() {
    int gid = blockIdx.x * blockDim.x + threadIdx.x;
    if (gid >= NROWS * 64) return;
    int c = gid & 63;
    int row = gid >> 6;
    int base = (row >> 9) << 9;
    const int* id = g_idx + row * Kn;
    float s = 0.f;
    #pragma unroll
    for (int k = 0; k < Kn; k++) s += g_X[(size_t)(base + id[k]) * 128 + c];
    g_X[(size_t)row * 128 + 64 + c] = s;
}

// ================= K2: gc2 GEMM fused with per-batch column max =================
__global__ __launch_bounds__(256) void gc2_kernel(const float* __restrict__ wroot2,
                                                  const float* __restrict__ wrel2,
                                                  const float* __restrict__ b2) {
    __shared__ float Xs[64 * 68];
    __shared__ float Ws[64 * 64];
    int n0 = blockIdx.x * 64;
    int r0 = blockIdx.y * 64;
    int tid = threadIdx.x;
    int tr = tid >> 4;
    int tc = tid & 15;

    float acc[4][4];
    #pragma unroll
    for (int i = 0; i < 4; i++)
        #pragma unroll
        for (int j = 0; j < 4; j++) acc[i][j] = 0.f;

    for (int kc = 0; kc < 2; kc++) {
        const float* W = kc ? wrel2 : wroot2;
        #pragma unroll
        for (int it = 0; it < 4; it++) {
            int lin = it * 256 + tid;
            int r = lin >> 4;
            int k4 = lin & 15;
            float4 v = *(const float4*)(g_X + (size_t)(r0 + r) * 128 + kc * 64 + k4 * 4);
            Xs[(k4 * 4 + 0) * 68 + r] = v.x;
            Xs[(k4 * 4 + 1) * 68 + r] = v.y;
            Xs[(k4 * 4 + 2) * 68 + r] = v.z;
            Xs[(k4 * 4 + 3) * 68 + r] = v.w;
            float4 wv = *(const float4*)(W + (size_t)r * 128 + n0 + k4 * 4);
            *(float4*)(Ws + r * 64 + k4 * 4) = wv;
        }
        __syncthreads();
        #pragma unroll
        for (int k = 0; k < 64; k++) {
            float4 a = *(const float4*)(Xs + k * 68 + tr * 4);
            float4 w = *(const float4*)(Ws + k * 64 + tc * 4);
            float av[4] = {a.x, a.y, a.z, a.w};
            float wv[4] = {w.x, w.y, w.z, w.w};
            #pragma unroll
            for (int i = 0; i < 4; i++)
                #pragma unroll
                for (int j = 0; j < 4; j++)
                    acc[i][j] = fmaf(av[i], wv[j], acc[i][j]);
        }
        __syncthreads();
    }

    float* sred = Xs;
    #pragma unroll
    for (int j = 0; j < 4; j++) {
        float m = fmaxf(fmaxf(acc[0][j], acc[1][j]), fmaxf(acc[2][j], acc[3][j]));
        sred[tr * 64 + tc * 4 + j] = m;
    }
    __syncthreads();
    if (tid < 64) {
        float m = sred[tid];
        #pragma unroll
        for (int t = 1; t < 16; t++) m = fmaxf(m, sred[t * 64 + tid]);
        m += b2[n0 + tid];
        int b = r0 >> 9;
        atomicMax(&g_proxy[b * SDn + n0 + tid], fenc(m));
    }
}

// ================= generic batched stage: Y[32][No] = act(X[32][K] @ W^T + b) =================
// one warp per output column o, all 32 batches in registers; weights read once.
template<int K, int XS, int YS, int ACT, bool DEC, bool WT, int WS>
__global__ __launch_bounds__(256) void stage_kernel(const void* __restrict__ Xv,
                                                    const float* __restrict__ W,
                                                    const float* __restrict__ bias,
                                                    float* __restrict__ Y,
                                                    const float* __restrict__ bn_g,
                                                    const float* __restrict__ bn_b,
                                                    const float* __restrict__ bn_m,
                                                    const float* __restrict__ bn_v) {
    __shared__ float red[8][32][33];
    int w = threadIdx.x >> 5, l = threadIdx.x & 31;
    int o = blockIdx.x * 8 + w;
    const float* Xf = (const float*)Xv;
    const unsigned* Xu = (const unsigned*)Xv;

    float acc[32];
    #pragma unroll
    for (int bb = 0; bb < 32; bb++) acc[bb] = 0.f;

    #pragma unroll 2
    for (int kc = 0; kc < K; kc += 32) {
        int k = kc + l;
        float wv = WT ? W[(size_t)k * WS + o] : W[(size_t)o * K + k];
        #pragma unroll
        for (int bb = 0; bb < 32; bb++) {
            float xv = DEC ? fdec(Xu[bb * XS + k]) : Xf[bb * XS + k];
            acc[bb] = fmaf(wv, xv, acc[bb]);
        }
    }

    #pragma unroll
    for (int bb = 0; bb < 32; bb++) red[w][bb][l] = acc[bb];
    __syncwarp();
    float s = 0.f;
    #pragma unroll
    for (int j = 0; j < 32; j++) s += red[w][l][j];
    s += bias[o];
    if (ACT == 1) {
        s = fmaf(bn_g[o] * (s - bn_m[o]), rsqrtf(bn_v[o] + 1e-5f), bn_b[o]);
        s = (s >= 0.f) ? s : 0.2f * s;
    }
    Y[(size_t)l * YS + o] = s;
}

// ================= base partials: partial[b][ks] = X[b][ks*128:+128] @ red_w rows =================
// grid (11 kchunks, 4 bgroups), block 192 (each thread = 2 output cols)
__global__ __launch_bounds__(192) void base_kernel(const float* __restrict__ red_w) {
    __shared__ float sx[8][128];
    int ks = blockIdx.x;
    int bg = blockIdx.y;
    int t = threadIdx.x;
    int k0 = ks * 128;
    for (int q = t; q < 8 * 128; q += 192) {
        int bb = q >> 7, kk = q & 127;
        sx[bb][kk] = g_g2qc[(size_t)(bg * 8 + bb) * 1408 + k0 + kk];
    }
    __syncthreads();
    float2 acc[8];
    #pragma unroll
    for (int bb = 0; bb < 8; bb++) { acc[bb].x = 0.f; acc[bb].y = 0.f; }
    const float* wp = red_w + (size_t)k0 * Cn + 2 * t;
    #pragma unroll 4
    for (int k = 0; k < 128; k++) {
        float2 wv = *(const float2*)(wp + (size_t)k * Cn);
        #pragma unroll
        for (int bb = 0; bb < 8; bb++) {
            float xv = sx[bb][k];
            acc[bb].x = fmaf(xv, wv.x, acc[bb].x);
            acc[bb].y = fmaf(xv, wv.y, acc[bb].y);
        }
    }
    #pragma unroll
    for (int bb = 0; bb < 8; bb++) {
        int b = bg * 8 + bb;
        *(float2*)(g_partial + (size_t)(b * 11 + ks) * Cn + 2 * t) = acc[bb];
    }
}

// ================= out =================
__global__ void out_kernel(const float* __restrict__ red_w, const float* __restrict__ red_b,
                           const float* __restrict__ coarse, float* __restrict__ out) {
    int gid = blockIdx.x * blockDim.x + threadIdx.x;
    if (gid >= Bn * Mn * (Cn / 4)) return;
    int qd = gid % (Cn / 4);
    int bm = gid / (Cn / 4);
    int b = bm / Mn;
    int c = qd * 4;

    float4 acc = *(const float4*)(red_b + c);
    #pragma unroll
    for (int ch = 0; ch < 11; ch++) {
        float4 p = *(const float4*)(g_partial + (b * 11 + ch) * Cn + c);
        acc.x += p.x; acc.y += p.y; acc.z += p.z; acc.w += p.w;
    }
    float c0 = coarse[bm * 3 + 0];
    float c1 = coarse[bm * 3 + 1];
    float c2 = coarse[bm * 3 + 2];
    float4 w0 = *(const float4*)(red_w + (size_t)1408 * Cn + c);
    float4 w1 = *(const float4*)(red_w + (size_t)1409 * Cn + c);
    float4 w2 = *(const float4*)(red_w + (size_t)1410 * Cn + c);
    acc.x += c0 * w0.x + c1 * w1.x + c2 * w2.x;
    acc.y += c0 * w0.y + c1 * w1.y + c2 * w2.y;
    acc.z += c0 * w0.z + c1 * w1.z + c2 * w2.z;
    acc.w += c0 * w0.w + c1 * w1.w + c2 * w2.w;
    *(float4*)(out + (size_t)bm * Cn + c) = acc;
}

// ---------------- launch ----------------
extern "C" void kernel_launch(void* const* d_in, const int* in_sizes, int n_in,
                              void* d_out, int out_size) {
    (void)in_sizes; (void)n_in; (void)out_size;
    const float* coarse     = (const float*)d_in[1];
    const float* skeleton   = (const float*)d_in[2];
    const float* gc1_wroot  = (const float*)d_in[3];
    const float* gc1_wrel   = (const float*)d_in[4];
    const float* gc1_b      = (const float*)d_in[5];
    const float* gc2_wroot  = (const float*)d_in[6];
    const float* gc2_wrel   = (const float*)d_in[7];
    const float* gc2_b      = (const float*)d_in[8];
    const float* proj_w     = (const float*)d_in[9];
    const float* proj_b     = (const float*)d_in[10];
    const float* attn_in_w  = (const float*)d_in[11];
    const float* attn_in_b  = (const float*)d_in[12];
    const float* attn_out_w = (const float*)d_in[13];
    const float* attn_out_b = (const float*)d_in[14];
    const float* inc1_w     = (const float*)d_in[15];
    const float* inc1_b     = (const float*)d_in[16];
    const float* bn_g       = (const float*)d_in[17];
    const float* bn_b       = (const float*)d_in[18];
    const float* bn_m       = (const float*)d_in[19];
    const float* bn_v       = (const float*)d_in[20];
    const float* inc2_w     = (const float*)d_in[21];
    const float* inc2_b     = (const float*)d_in[22];
    const float* red_w      = (const float*)d_in[23];
    const float* red_b      = (const float*)d_in[24];
    float* out = (float*)d_out;

    void *p_proxy, *p_kv, *p_vh, *p_g2qc, *p_g1;
    cudaGetSymbolAddress(&p_proxy, g_proxy);
    cudaGetSymbolAddress(&p_kv, g_kv);
    cudaGetSymbolAddress(&p_vh, g_vh);
    cudaGetSymbolAddress(&p_g2qc, g_g2qc);
    cudaGetSymbolAddress(&p_g1, g_g1);
    float* f_kv = (float*)p_kv;
    float* f_vh = (float*)p_vh;
    float* f_g2qc = (float*)p_g2qc;
    float* f_g1 = (float*)p_g1;

    knn_gc1_kernel<<<dim3(Bn, 4), 512>>>(skeleton, gc1_wroot, gc1_wrel, gc1_b);
    agg_kernel<<<(NROWS * 64) / 256, 256>>>();
    gc2_kernel<<<dim3(2, NROWS / 64), 256>>>(gc2_wroot, gc2_wrel, gc2_b);

    // kv = proxy @ proj_w + proj_b   (W transposed layout)
    stage_kernel<128, 128, 384, 0, true, true, 384><<<48, 256>>>(
        p_proxy, proj_w, proj_b, f_kv, nullptr, nullptr, nullptr, nullptr);
    // vh = kv @ wv^T + bv
    stage_kernel<384, 384, 384, 0, false, false, 0><<<48, 256>>>(
        p_kv, attn_in_w + 2 * Cn * Cn, attn_in_b + 2 * Cn, f_vh, nullptr, nullptr, nullptr, nullptr);
    // qc = vh @ attn_out^T + b
    stage_kernel<384, 384, 1408, 0, false, false, 0><<<48, 256>>>(
        p_vh, attn_out_w, attn_out_b, f_g2qc + 1024, nullptr, nullptr, nullptr, nullptr);
    // g1 = leaky(BN(qc @ inc1^T + b1))
    stage_kernel<384, 1408, 1024, 1, false, false, 0><<<128, 256>>>(
        (const char*)p_g2qc + 1024 * sizeof(float), inc1_w, inc1_b, f_g1, bn_g, bn_b, bn_m, bn_v);
    // g2 = g1 @ inc2^T + b2
    stage_kernel<1024, 1024, 1408, 0, false, false, 0><<<128, 256>>>(
        p_g1, inc2_w, inc2_b, f_g2qc, nullptr, nullptr, nullptr, nullptr);

    base_kernel<<<dim3(11, 4), 192>>>(red_w);
    out_kernel<<<(Bn * Mn * (Cn / 4) + 255) / 256, 256>>>(red_w, red_b, coarse, out);
}

// round 4
// speedup vs baseline: 1.2307x; 1.2307x over previous
#include <cuda_runtime.h>
#include <cstdint>

// ---------------- constants ----------------
#define Bn 32
#define Mn 448
#define Cn 384
#define Sn 512
#define SDn 128
#define Kn 8
#define NROWS (Bn * Sn)   // 16384

// ---------------- scratch ----------------
__device__ int      g_idx[NROWS * Kn];
__device__ float    g_X[NROWS * 128];        // [row][0:64]=h1(relu), [64:128]=agg1
__device__ unsigned g_proxy[Bn * SDn];       // encoded float max
__device__ float    g_g2qc[Bn * 1408];       // [0:1024]=g2, [1024:1408]=qc
__device__ float    g_g1[Bn * 1024];
__device__ float    g_base[Bn * Cn];         // final base incl. red_b
__device__ float    g_redwT[Cn * 1408];      // red_w[0:1408,:] transposed

// ---------------- helpers ----------------
__device__ __forceinline__ unsigned fenc(float f) {
    unsigned u = __float_as_uint(f);
    return (u & 0x80000000u) ? ~u : (u | 0x80000000u);
}
__device__ __forceinline__ float fdec(unsigned e) {
    unsigned u = (e & 0x80000000u) ? (e ^ 0x80000000u) : ~e;
    return __uint_as_float(u);
}
__device__ __forceinline__ float warp_sum(float v) {
    #pragma unroll
    for (int off = 16; off; off >>= 1) v += __shfl_down_sync(0xffffffffu, v, off);
    return v;
}

// ================= K0: fused knn + gc1 =================
__global__ __launch_bounds__(512) void knn_gc1_kernel(const float* __restrict__ skel,
                                                      const float* __restrict__ wroot,
                                                      const float* __restrict__ wrel,
                                                      const float* __restrict__ bias) {
    __shared__ float sx[Sn], sy[Sn], sz[Sn];
    __shared__ float cd[128 * 32];
    __shared__ int   ci[128 * 32];
    __shared__ float wgt[448];
    int b = blockIdx.x;
    int t = threadIdx.x;
    const float* sk = skel + (size_t)b * Sn * 3;

    #pragma unroll
    for (int q = t; q < Sn * 3; q += 512) {
        float v = sk[q];
        int idx = q / 3, r = q - idx * 3;
        if (r == 0) sx[idx] = v; else if (r == 1) sy[idx] = v; else sz[idx] = v;
    }
    if (blockIdx.y == 0 && t < SDn) g_proxy[b * SDn + t] = 0u;
    if (t < 448) wgt[t] = (t < 192) ? wroot[t] : ((t < 384) ? wrel[t - 192] : bias[t - 384]);
    __syncthreads();

    int p = t >> 2, s4 = t & 3;
    int i = blockIdx.y * 128 + p;
    float xi = sx[i], yi = sy[i], zi = sz[i];

    float bd[8]; int bi8[8];
    #pragma unroll
    for (int k = 0; k < 8; k++) { bd[k] = 3.0e38f; bi8[k] = 0; }

    for (int jj = 0; jj < 128; jj++) {
        int j = jj * 4 + s4;
        float dx = xi - sx[j], dy = yi - sy[j], dz = zi - sz[j];
        float d = fmaf(dx, dx, fmaf(dy, dy, dz * dz));
        if (j == i) d = 3.0e38f;
        if (d < bd[7]) {
            bd[7] = d; bi8[7] = j;
            #pragma unroll
            for (int k = 7; k > 0; k--) {
                if (bd[k] < bd[k - 1]) {
                    float td = bd[k]; bd[k] = bd[k - 1]; bd[k - 1] = td;
                    int ti = bi8[k]; bi8[k] = bi8[k - 1]; bi8[k - 1] = ti;
                }
            }
        }
    }
    #pragma unroll
    for (int k = 0; k < 8; k++) { cd[p * 32 + s4 * 8 + k] = bd[k]; ci[p * 32 + s4 * 8 + k] = bi8[k]; }
    __syncthreads();

    if (t < 128) {
        float fd[8]; int fi[8];
        #pragma unroll
        for (int k = 0; k < 8; k++) { fd[k] = 3.0e38f; fi[k] = 0; }
        for (int s = 0; s < 4; s++) {
            #pragma unroll
            for (int k = 0; k < 8; k++) {
                float d = cd[t * 32 + s * 8 + k];
                if (d >= fd[7]) break;
                int j = ci[t * 32 + s * 8 + k];
                fd[7] = d; fi[7] = j;
                #pragma unroll
                for (int m = 7; m > 0; m--) {
                    if (fd[m] < fd[m - 1]) {
                        float td = fd[m]; fd[m] = fd[m - 1]; fd[m - 1] = td;
                        int ti = fi[m]; fi[m] = fi[m - 1]; fi[m - 1] = ti;
                    }
                }
            }
        }
        int ip = blockIdx.y * 128 + t;
        int row = b * Sn + ip;
        float a0 = 0.f, a1 = 0.f, a2 = 0.f;
        #pragma unroll
        for (int k = 0; k < 8; k++) {
            int j = fi[k];
            g_idx[row * Kn + k] = j;
            a0 += sx[j]; a1 += sy[j]; a2 += sz[j];
        }
        float x0 = sx[ip], x1 = sy[ip], x2 = sz[ip];
        float* cif = (float*)ci;
        #pragma unroll
        for (int ch = 0; ch < 64; ch++) {
            float h = wgt[384 + ch];
            h = fmaf(x0, wgt[0 * 64 + ch], h);
            h = fmaf(x1, wgt[1 * 64 + ch], h);
            h = fmaf(x2, wgt[2 * 64 + ch], h);
            h = fmaf(a0, wgt[192 + 0 * 64 + ch], h);
            h = fmaf(a1, wgt[192 + 1 * 64 + ch], h);
            h = fmaf(a2, wgt[192 + 2 * 64 + ch], h);
            h = fmaxf(h, 0.f);
            if (ch < 32) cd[t * 32 + ch] = h; else cif[t * 32 + ch - 32] = h;
        }
    }
    __syncthreads();

    float* cif = (float*)ci;
    #pragma unroll
    for (int q = t; q < 128 * 64; q += 512) {
        int p2 = q >> 6, ch = q & 63;
        float v = (ch < 32) ? cd[p2 * 32 + ch] : cif[p2 * 32 + ch - 32];
        g_X[(size_t)(b * Sn + blockIdx.y * 128 + p2) * 128 + ch] = v;
    }
}

// ================= K1: neighbor aggregation of h1 =================
__global__ void agg_kernel() {
    int gid = blockIdx.x * blockDim.x + threadIdx.x;
    if (gid >= NROWS * 64) return;
    int c = gid & 63;
    int row = gid >> 6;
    int base = (row >> 9) << 9;
    const int* id = g_idx + row * Kn;
    float s = 0.f;
    #pragma unroll
    for (int k = 0; k < Kn; k++) s += g_X[(size_t)(base + id[k]) * 128 + c];
    g_X[(size_t)row * 128 + 64 + c] = s;
}

// ================= K2: gc2 GEMM fused with per-batch column max =================
__global__ __launch_bounds__(256) void gc2_kernel(const float* __restrict__ wroot2,
                                                  const float* __restrict__ wrel2,
                                                  const float* __restrict__ b2) {
    __shared__ float Xs[64 * 68];
    __shared__ float Ws[64 * 64];
    int n0 = blockIdx.x * 64;
    int r0 = blockIdx.y * 64;
    int tid = threadIdx.x;
    int tr = tid >> 4;
    int tc = tid & 15;

    float acc[4][4];
    #pragma unroll
    for (int i = 0; i < 4; i++)
        #pragma unroll
        for (int j = 0; j < 4; j++) acc[i][j] = 0.f;

    for (int kc = 0; kc < 2; kc++) {
        const float* W = kc ? wrel2 : wroot2;
        #pragma unroll
        for (int it = 0; it < 4; it++) {
            int lin = it * 256 + tid;
            int r = lin >> 4;
            int k4 = lin & 15;
            float4 v = *(const float4*)(g_X + (size_t)(r0 + r) * 128 + kc * 64 + k4 * 4);
            Xs[(k4 * 4 + 0) * 68 + r] = v.x;
            Xs[(k4 * 4 + 1) * 68 + r] = v.y;
            Xs[(k4 * 4 + 2) * 68 + r] = v.z;
            Xs[(k4 * 4 + 3) * 68 + r] = v.w;
            float4 wv = *(const float4*)(W + (size_t)r * 128 + n0 + k4 * 4);
            *(float4*)(Ws + r * 64 + k4 * 4) = wv;
        }
        __syncthreads();
        #pragma unroll
        for (int k = 0; k < 64; k++) {
            float4 a = *(const float4*)(Xs + k * 68 + tr * 4);
            float4 w = *(const float4*)(Ws + k * 64 + tc * 4);
            float av[4] = {a.x, a.y, a.z, a.w};
            float wv[4] = {w.x, w.y, w.z, w.w};
            #pragma unroll
            for (int i = 0; i < 4; i++)
                #pragma unroll
                for (int j = 0; j < 4; j++)
                    acc[i][j] = fmaf(av[i], wv[j], acc[i][j]);
        }
        __syncthreads();
    }

    float* sred = Xs;
    #pragma unroll
    for (int j = 0; j < 4; j++) {
        float m = fmaxf(fmaxf(acc[0][j], acc[1][j]), fmaxf(acc[2][j], acc[3][j]));
        sred[tr * 64 + tc * 4 + j] = m;
    }
    __syncthreads();
    if (tid < 64) {
        float m = sred[tid];
        #pragma unroll
        for (int t = 1; t < 16; t++) m = fmaxf(m, sred[t * 64 + tid]);
        m += b2[n0 + tid];
        int b = r0 >> 9;
        atomicMax(&g_proxy[b * SDn + n0 + tid], fenc(m));
    }
}

// ================= K3: per-batch chain: proxy->kv->vh(=ctx)->qc (round-2 proven) =================
__global__ void chain1_kernel(const float* __restrict__ proj_w, const float* __restrict__ proj_b,
                              const float* __restrict__ attn_in_w, const float* __restrict__ attn_in_b,
                              const float* __restrict__ attn_out_w, const float* __restrict__ attn_out_b) {
    int b = blockIdx.x;
    int tid = threadIdx.x; // 384
    __shared__ float sp[SDn], skv[Cn], svh[Cn];
    if (tid < SDn) sp[tid] = fdec(g_proxy[b * SDn + tid]);
    __syncthreads();

    float acc = proj_b[tid];
    #pragma unroll 8
    for (int k = 0; k < SDn; k++) acc = fmaf(sp[k], proj_w[k * Cn + tid], acc);
    skv[tid] = acc;
    __syncthreads();

    int w = tid >> 5, l = tid & 31;

    for (int t = 0; t < 32; t++) {
        int c = w * 32 + t;
        const float* row = attn_in_w + (size_t)(2 * Cn + c) * Cn;
        float p = 0.f;
        #pragma unroll
        for (int j = l; j < Cn; j += 32) p = fmaf(skv[j], row[j], p);
        p = warp_sum(p);
        if (l == 0) svh[c] = p + attn_in_b[2 * Cn + c];
    }
    __syncthreads();

    for (int t = 0; t < 32; t++) {
        int c = w * 32 + t;
        const float* row = attn_out_w + (size_t)c * Cn;
        float p = 0.f;
        #pragma unroll
        for (int j = l; j < Cn; j += 32) p = fmaf(svh[j], row[j], p);
        p = warp_sum(p);
        if (l == 0) g_g2qc[b * 1408 + 1024 + c] = p + attn_out_b[c];
    }
}

// ================= transpose red_w[0:1408,0:384] -> g_redwT[384][1408] =================
__global__ __launch_bounds__(256) void redw_transpose_kernel(const float* __restrict__ red_w) {
    __shared__ float tile[32][33];
    int k0 = blockIdx.x * 32;   // 44 tiles
    int o0 = blockIdx.y * 32;   // 12 tiles
    int tx = threadIdx.x & 31, ty = threadIdx.x >> 5; // 32x8
    #pragma unroll
    for (int j = 0; j < 4; j++)
        tile[ty + j * 8][tx] = red_w[(size_t)(k0 + ty + j * 8) * Cn + o0 + tx];
    __syncthreads();
    #pragma unroll
    for (int j = 0; j < 4; j++)
        g_redwT[(size_t)(o0 + ty + j * 8) * 1408 + k0 + tx] = tile[tx][ty + j * 8];
}

// ================= stageM: Y[8 batches][128 outs] = act(X @ W^T + b), weights read once per bgroup =================
// grid (Nout/128, 4). block 256 (8 warps). W row-major (Nout, K).
template<int K, int ACT>
__global__ __launch_bounds__(256) void stageM_kernel(const float* __restrict__ X, int XS,
                                                     const float* __restrict__ W,
                                                     const float* __restrict__ bias,
                                                     float* __restrict__ Y, int YS,
                                                     const float* __restrict__ bn_g,
                                                     const float* __restrict__ bn_b,
                                                     const float* __restrict__ bn_m,
                                                     const float* __restrict__ bn_v) {
    __shared__ float4 Xs[8][K / 4];
    int tid = threadIdx.x;
    int bg = blockIdx.y;
    int w = tid >> 5, l = tid & 31;

    for (int q = tid; q < 8 * (K / 4); q += 256) {
        int bb = q / (K / 4);
        int kq = q % (K / 4);
        Xs[bb][kq] = *(const float4*)(X + (size_t)(bg * 8 + bb) * XS + kq * 4);
    }
    __syncthreads();

    for (int r = 0; r < 16; r++) {
        int o = blockIdx.x * 128 + w * 16 + r;
        const float4* Wrow = (const float4*)(W + (size_t)o * K);
        float acc[8];
        #pragma unroll
        for (int bb = 0; bb < 8; bb++) acc[bb] = 0.f;
        #pragma unroll
        for (int ki = 0; ki < K / 128; ki++) {
            int kq = ki * 32 + l;
            float4 wv = Wrow[kq];
            #pragma unroll
            for (int bb = 0; bb < 8; bb++) {
                float4 xv = Xs[bb][kq];
                float s = fmaf(wv.x, xv.x, fmaf(wv.y, xv.y, fmaf(wv.z, xv.z, wv.w * xv.w)));
                acc[bb] += s;
            }
        }
        #pragma unroll
        for (int off = 16; off; off >>= 1)
            #pragma unroll
            for (int bb = 0; bb < 8; bb++)
                acc[bb] += __shfl_xor_sync(0xffffffffu, acc[bb], off);
        if (l < 8) {
            float s = acc[l] + bias[o];
            if (ACT == 1) {
                s = fmaf(bn_g[o] * (s - bn_m[o]), rsqrtf(bn_v[o] + 1e-5f), bn_b[o]);
                s = (s >= 0.f) ? s : 0.2f * s;
            }
            Y[(size_t)(bg * 8 + l) * YS + o] = s;
        }
    }
}

// ================= out: out[b,m,c] = base[b][c] + coarse[b,m]·red_w[1408:1411] =================
__global__ void out_kernel(const float* __restrict__ red_w,
                           const float* __restrict__ coarse, float* __restrict__ out) {
    int gid = blockIdx.x * blockDim.x + threadIdx.x;
    if (gid >= Bn * Mn * (Cn / 4)) return;
    int qd = gid % (Cn / 4);
    int bm = gid / (Cn / 4);
    int b = bm / Mn;
    int c = qd * 4;

    float4 acc = *(const float4*)(g_base + b * Cn + c);
    float c0 = coarse[bm * 3 + 0];
    float c1 = coarse[bm * 3 + 1];
    float c2 = coarse[bm * 3 + 2];
    float4 w0 = *(const float4*)(red_w + (size_t)1408 * Cn + c);
    float4 w1 = *(const float4*)(red_w + (size_t)1409 * Cn + c);
    float4 w2 = *(const float4*)(red_w + (size_t)1410 * Cn + c);
    acc.x += c0 * w0.x + c1 * w1.x + c2 * w2.x;
    acc.y += c0 * w0.y + c1 * w1.y + c2 * w2.y;
    acc.z += c0 * w0.z + c1 * w1.z + c2 * w2.z;
    acc.w += c0 * w0.w + c1 * w1.w + c2 * w2.w;
    *(float4*)(out + (size_t)bm * Cn + c) = acc;
}

// ---------------- launch ----------------
extern "C" void kernel_launch(void* const* d_in, const int* in_sizes, int n_in,
                              void* d_out, int out_size) {
    (void)in_sizes; (void)n_in; (void)out_size;
    const float* coarse     = (const float*)d_in[1];
    const float* skeleton   = (const float*)d_in[2];
    const float* gc1_wroot  = (const float*)d_in[3];
    const float* gc1_wrel   = (const float*)d_in[4];
    const float* gc1_b      = (const float*)d_in[5];
    const float* gc2_wroot  = (const float*)d_in[6];
    const float* gc2_wrel   = (const float*)d_in[7];
    const float* gc2_b      = (const float*)d_in[8];
    const float* proj_w     = (const float*)d_in[9];
    const float* proj_b     = (const float*)d_in[10];
    const float* attn_in_w  = (const float*)d_in[11];
    const float* attn_in_b  = (const float*)d_in[12];
    const float* attn_out_w = (const float*)d_in[13];
    const float* attn_out_b = (const float*)d_in[14];
    const float* inc1_w     = (const float*)d_in[15];
    const float* inc1_b     = (const float*)d_in[16];
    const float* bn_g       = (const float*)d_in[17];
    const float* bn_b       = (const float*)d_in[18];
    const float* bn_m       = (const float*)d_in[19];
    const float* bn_v       = (const float*)d_in[20];
    const float* inc2_w     = (const float*)d_in[21];
    const float* inc2_b     = (const float*)d_in[22];
    const float* red_w      = (const float*)d_in[23];
    const float* red_b      = (const float*)d_in[24];
    float* out = (float*)d_out;

    void *p_g2qc, *p_g1, *p_redwT;
    cudaGetSymbolAddress(&p_g2qc, g_g2qc);
    cudaGetSymbolAddress(&p_g1, g_g1);
    cudaGetSymbolAddress(&p_redwT, g_redwT);
    float* f_g2qc = (float*)p_g2qc;
    float* f_g1 = (float*)p_g1;
    float* f_redwT = (float*)p_redwT;

    void* p_base;
    cudaGetSymbolAddress(&p_base, g_base);
    float* f_base = (float*)p_base;

    redw_transpose_kernel<<<dim3(44, 12), 256>>>(red_w);
    knn_gc1_kernel<<<dim3(Bn, 4), 512>>>(skeleton, gc1_wroot, gc1_wrel, gc1_b);
    agg_kernel<<<(NROWS * 64) / 256, 256>>>();
    gc2_kernel<<<dim3(2, NROWS / 64), 256>>>(gc2_wroot, gc2_wrel, gc2_b);
    chain1_kernel<<<Bn, Cn>>>(proj_w, proj_b, attn_in_w, attn_in_b, attn_out_w, attn_out_b);

    // g1 = leaky(BN(qc @ inc1^T + b1));  qc at g_g2qc + 1024, row stride 1408
    stageM_kernel<384, 1><<<dim3(8, 4), 256>>>(f_g2qc + 1024, 1408, inc1_w, inc1_b,
                                               f_g1, 1024, bn_g, bn_b, bn_m, bn_v);
    // g2 = g1 @ inc2^T + b2  -> g_g2qc[:,0:1024]
    stageM_kernel<1024, 0><<<dim3(8, 4), 256>>>(f_g1, 1024, inc2_w, inc2_b,
                                                f_g2qc, 1408, nullptr, nullptr, nullptr, nullptr);
    // base = [g2, qc] @ red_w[0:1408] + red_b  (uses transposed red_w)
    stageM_kernel<1408, 0><<<dim3(3, 4), 256>>>(f_g2qc, 1408, f_redwT, red_b,
                                                f_base, Cn, nullptr, nullptr, nullptr, nullptr);

    out_kernel<<<(Bn * Mn * (Cn / 4) + 255) / 256, 256>>>(red_w, coarse, out);
}

// round 6
// speedup vs baseline: 1.9868x; 1.6143x over previous
#include <cuda_runtime.h>
#include <cstdint>

// ---------------- constants ----------------
#define Bn 32
#define Mn 448
#define Cn 384
#define Sn 512
#define SDn 128
#define Kn 8
#define NROWS (Bn * Sn)   // 16384

// ---------------- scratch ----------------
__device__ int      g_idx[NROWS * Kn];
__device__ float    g_X[NROWS * 128];        // [row][0:64]=h1(relu), [64:128]=agg1
__device__ unsigned g_proxy[Bn * SDn];       // encoded float max
__device__ float    g_g2qc[Bn * 1408];       // [0:1024]=g2, [1024:1408]=qc
__device__ float    g_g1[Bn * 1024];
__device__ float    g_base[Bn * Cn];         // final base incl. red_b
__device__ float    g_redwT[Cn * 1408];      // red_w[0:1408,:] transposed

// ---------------- helpers ----------------
__device__ __forceinline__ unsigned fenc(float f) {
    unsigned u = __float_as_uint(f);
    return (u & 0x80000000u) ? ~u : (u | 0x80000000u);
}
__device__ __forceinline__ float fdec(unsigned e) {
    unsigned u = (e & 0x80000000u) ? (e ^ 0x80000000u) : ~e;
    return __uint_as_float(u);
}

// ================= K0: fused knn + gc1 =================
__global__ __launch_bounds__(512) void knn_gc1_kernel(const float* __restrict__ skel,
                                                      const float* __restrict__ wroot,
                                                      const float* __restrict__ wrel,
                                                      const float* __restrict__ bias) {
    __shared__ float sx[Sn], sy[Sn], sz[Sn];
    __shared__ float cd[128 * 32];
    __shared__ int   ci[128 * 32];
    __shared__ float wgt[448];
    int b = blockIdx.x;
    int t = threadIdx.x;
    const float* sk = skel + (size_t)b * Sn * 3;

    #pragma unroll
    for (int q = t; q < Sn * 3; q += 512) {
        float v = sk[q];
        int idx = q / 3, r = q - idx * 3;
        if (r == 0) sx[idx] = v; else if (r == 1) sy[idx] = v; else sz[idx] = v;
    }
    if (blockIdx.y == 0 && t < SDn) g_proxy[b * SDn + t] = 0u;
    if (t < 448) wgt[t] = (t < 192) ? wroot[t] : ((t < 384) ? wrel[t - 192] : bias[t - 384]);
    __syncthreads();

    int p = t >> 2, s4 = t & 3;
    int i = blockIdx.y * 128 + p;
    float xi = sx[i], yi = sy[i], zi = sz[i];

    float bd[8]; int bi8[8];
    #pragma unroll
    for (int k = 0; k < 8; k++) { bd[k] = 3.0e38f; bi8[k] = 0; }

    for (int jj = 0; jj < 128; jj++) {
        int j = jj * 4 + s4;
        float dx = xi - sx[j], dy = yi - sy[j], dz = zi - sz[j];
        float d = fmaf(dx, dx, fmaf(dy, dy, dz * dz));
        if (j == i) d = 3.0e38f;
        if (d < bd[7]) {
            bd[7] = d; bi8[7] = j;
            #pragma unroll
            for (int k = 7; k > 0; k--) {
                if (bd[k] < bd[k - 1]) {
                    float td = bd[k]; bd[k] = bd[k - 1]; bd[k - 1] = td;
                    int ti = bi8[k]; bi8[k] = bi8[k - 1]; bi8[k - 1] = ti;
                }
            }
        }
    }
    #pragma unroll
    for (int k = 0; k < 8; k++) { cd[p * 32 + s4 * 8 + k] = bd[k]; ci[p * 32 + s4 * 8 + k] = bi8[k]; }
    __syncthreads();

    if (t < 128) {
        float fd[8]; int fi[8];
        #pragma unroll
        for (int k = 0; k < 8; k++) { fd[k] = 3.0e38f; fi[k] = 0; }
        for (int s = 0; s < 4; s++) {
            #pragma unroll
            for (int k = 0; k < 8; k++) {
                float d = cd[t * 32 + s * 8 + k];
                if (d >= fd[7]) break;
                int j = ci[t * 32 + s * 8 + k];
                fd[7] = d; fi[7] = j;
                #pragma unroll
                for (int m = 7; m > 0; m--) {
                    if (fd[m] < fd[m - 1]) {
                        float td = fd[m]; fd[m] = fd[m - 1]; fd[m - 1] = td;
                        int ti = fi[m]; fi[m] = fi[m - 1]; fi[m - 1] = ti;
                    }
                }
            }
        }
        int ip = blockIdx.y * 128 + t;
        int row = b * Sn + ip;
        float a0 = 0.f, a1 = 0.f, a2 = 0.f;
        #pragma unroll
        for (int k = 0; k < 8; k++) {
            int j = fi[k];
            g_idx[row * Kn + k] = j;
            a0 += sx[j]; a1 += sy[j]; a2 += sz[j];
        }
        float x0 = sx[ip], x1 = sy[ip], x2 = sz[ip];
        float* cif = (float*)ci;
        #pragma unroll
        for (int ch = 0; ch < 64; ch++) {
            float h = wgt[384 + ch];
            h = fmaf(x0, wgt[0 * 64 + ch], h);
            h = fmaf(x1, wgt[1 * 64 + ch], h);
            h = fmaf(x2, wgt[2 * 64 + ch], h);
            h = fmaf(a0, wgt[192 + 0 * 64 + ch], h);
            h = fmaf(a1, wgt[192 + 1 * 64 + ch], h);
            h = fmaf(a2, wgt[192 + 2 * 64 + ch], h);
            h = fmaxf(h, 0.f);
            if (ch < 32) cd[t * 32 + ch] = h; else cif[t * 32 + ch - 32] = h;
        }
    }
    __syncthreads();

    float* cif = (float*)ci;
    #pragma unroll
    for (int q = t; q < 128 * 64; q += 512) {
        int p2 = q >> 6, ch = q & 63;
        float v = (ch < 32) ? cd[p2 * 32 + ch] : cif[p2 * 32 + ch - 32];
        g_X[(size_t)(b * Sn + blockIdx.y * 128 + p2) * 128 + ch] = v;
    }
}

// ================= K1: neighbor aggregation of h1 =================
__global__ void agg_kernel() {
    int gid = blockIdx.x * blockDim.x + threadIdx.x;
    if (gid >= NROWS * 64) return;
    int c = gid & 63;
    int row = gid >> 6;
    int base = (row >> 9) << 9;
    const int* id = g_idx + row * Kn;
    float s = 0.f;
    #pragma unroll
    for (int k = 0; k < Kn; k++) s += g_X[(size_t)(base + id[k]) * 128 + c];
    g_X[(size_t)row * 128 + 64 + c] = s;
}

// ================= K2: gc2 GEMM (128x128 tile, 8x8 thread tile) + per-batch column max =================
// grid 128 blocks (one 128-row tile each; 4 blocks per batch), block 256
__global__ __launch_bounds__(256) void gc2_kernel(const float* __restrict__ wroot2,
                                                  const float* __restrict__ wrel2,
                                                  const float* __restrict__ b2) {
    __shared__ __align__(16) float Xs[16 * 132];
    __shared__ __align__(16) float Ws[16 * 128];
    __shared__ __align__(16) float red[16 * 128];
    int r0 = blockIdx.x * 128;
    int tid = threadIdx.x;
    int ty = tid >> 4, tx = tid & 15;

    float acc[8][8];
    #pragma unroll
    for (int i = 0; i < 8; i++)
        #pragma unroll
        for (int j = 0; j < 8; j++) acc[i][j] = 0.f;

    for (int ch = 0; ch < 8; ch++) {
        int kc = ch * 16;
        const float* W = (kc < 64) ? (wroot2 + (size_t)kc * 128) : (wrel2 + (size_t)(kc - 64) * 128);
        #pragma unroll
        for (int it = 0; it < 2; it++) {
            int q = it * 256 + tid;
            int r = q >> 2, quad = q & 3;
            float4 v = *(const float4*)(g_X + (size_t)(r0 + r) * 128 + kc + quad * 4);
            Xs[(quad * 4 + 0) * 132 + r] = v.x;
            Xs[(quad * 4 + 1) * 132 + r] = v.y;
            Xs[(quad * 4 + 2) * 132 + r] = v.z;
            Xs[(quad * 4 + 3) * 132 + r] = v.w;
        }
        // 16 rows x 128 cols = 512 float4s: k = q>>5 (0..15), quad = q&31 (0..31)
        #pragma unroll
        for (int it = 0; it < 2; it++) {
            int q = it * 256 + tid;
            int k = q >> 5, c4 = q & 31;
            *(float4*)(Ws + k * 128 + c4 * 4) = *(const float4*)(W + (size_t)k * 128 + c4 * 4);
        }
        __syncthreads();
        #pragma unroll
        for (int k = 0; k < 16; k++) {
            float a[8], bv[8];
            *(float4*)(a)      = *(const float4*)(Xs + k * 132 + ty * 8);
            *(float4*)(a + 4)  = *(const float4*)(Xs + k * 132 + ty * 8 + 4);
            *(float4*)(bv)     = *(const float4*)(Ws + k * 128 + tx * 8);
            *(float4*)(bv + 4) = *(const float4*)(Ws + k * 128 + tx * 8 + 4);
            #pragma unroll
            for (int i = 0; i < 8; i++)
                #pragma unroll
                for (int j = 0; j < 8; j++)
                    acc[i][j] = fmaf(a[i], bv[j], acc[i][j]);
        }
        __syncthreads();
    }

    // per-thread column max over its 8 rows, then cross-ty reduce
    #pragma unroll
    for (int j = 0; j < 8; j++) {
        float m = acc[0][j];
        #pragma unroll
        for (int i = 1; i < 8; i++) m = fmaxf(m, acc[i][j]);
        red[ty * 128 + tx * 8 + j] = m;
    }
    __syncthreads();
    if (tid < 128) {
        float m = red[tid];
        #pragma unroll
        for (int t = 1; t < 16; t++) m = fmaxf(m, red[t * 128 + tid]);
        m += b2[tid];
        int b = r0 >> 9;
        atomicMax(&g_proxy[b * SDn + tid], fenc(m));
    }
}

// ================= K3: per-batch chain proxy->kv->vh->qc with 4-way ILP =================
__global__ __launch_bounds__(384) void chain1_kernel(const float* __restrict__ proj_w, const float* __restrict__ proj_b,
                              const float* __restrict__ attn_in_w, const float* __restrict__ attn_in_b,
                              const float* __restrict__ attn_out_w, const float* __restrict__ attn_out_b) {
    int b = blockIdx.x;
    int tid = threadIdx.x; // 384
    __shared__ float sp[SDn], skv[Cn], svh[Cn];
    if (tid < SDn) sp[tid] = fdec(g_proxy[b * SDn + tid]);
    __syncthreads();

    float acc = proj_b[tid];
    #pragma unroll 8
    for (int k = 0; k < SDn; k++) acc = fmaf(sp[k], proj_w[k * Cn + tid], acc);
    skv[tid] = acc;
    __syncthreads();

    int w = tid >> 5, l = tid & 31;

    // vh = kv @ wv^T + bv : each warp does 8 tiles of 4 outputs
    for (int t = 0; t < 8; t++) {
        int c0 = w * 32 + t * 4;
        const float* r0 = attn_in_w + (size_t)(2 * Cn + c0) * Cn;
        float p0 = 0.f, p1 = 0.f, p2 = 0.f, p3 = 0.f;
        #pragma unroll
        for (int j = l; j < Cn; j += 32) {
            float s = skv[j];
            p0 = fmaf(s, r0[j], p0);
            p1 = fmaf(s, r0[Cn + j], p1);
            p2 = fmaf(s, r0[2 * Cn + j], p2);
            p3 = fmaf(s, r0[3 * Cn + j], p3);
        }
        #pragma unroll
        for (int off = 16; off; off >>= 1) {
            p0 += __shfl_xor_sync(0xffffffffu, p0, off);
            p1 += __shfl_xor_sync(0xffffffffu, p1, off);
            p2 += __shfl_xor_sync(0xffffffffu, p2, off);
            p3 += __shfl_xor_sync(0xffffffffu, p3, off);
        }
        if (l == 0) {
            svh[c0 + 0] = p0 + attn_in_b[2 * Cn + c0 + 0];
            svh[c0 + 1] = p1 + attn_in_b[2 * Cn + c0 + 1];
            svh[c0 + 2] = p2 + attn_in_b[2 * Cn + c0 + 2];
            svh[c0 + 3] = p3 + attn_in_b[2 * Cn + c0 + 3];
        }
    }
    __syncthreads();

    // qc = vh @ attn_out^T + b
    for (int t = 0; t < 8; t++) {
        int c0 = w * 32 + t * 4;
        const float* r0 = attn_out_w + (size_t)c0 * Cn;
        float p0 = 0.f, p1 = 0.f, p2 = 0.f, p3 = 0.f;
        #pragma unroll
        for (int j = l; j < Cn; j += 32) {
            float s = svh[j];
            p0 = fmaf(s, r0[j], p0);
            p1 = fmaf(s, r0[Cn + j], p1);
            p2 = fmaf(s, r0[2 * Cn + j], p2);
            p3 = fmaf(s, r0[3 * Cn + j], p3);
        }
        #pragma unroll
        for (int off = 16; off; off >>= 1) {
            p0 += __shfl_xor_sync(0xffffffffu, p0, off);
            p1 += __shfl_xor_sync(0xffffffffu, p1, off);
            p2 += __shfl_xor_sync(0xffffffffu, p2, off);
            p3 += __shfl_xor_sync(0xffffffffu, p3, off);
        }
        if (l == 0) {
            g_g2qc[b * 1408 + 1024 + c0 + 0] = p0 + attn_out_b[c0 + 0];
            g_g2qc[b * 1408 + 1024 + c0 + 1] = p1 + attn_out_b[c0 + 1];
            g_g2qc[b * 1408 + 1024 + c0 + 2] = p2 + attn_out_b[c0 + 2];
            g_g2qc[b * 1408 + 1024 + c0 + 3] = p3 + attn_out_b[c0 + 3];
        }
    }
}

// ================= transpose red_w[0:1408,0:384] -> g_redwT[384][1408] =================
__global__ __launch_bounds__(256) void redw_transpose_kernel(const float* __restrict__ red_w) {
    __shared__ float tile[32][33];
    int k0 = blockIdx.x * 32;   // 44 tiles
    int o0 = blockIdx.y * 32;   // 12 tiles
    int tx = threadIdx.x & 31, ty = threadIdx.x >> 5; // 32x8
    #pragma unroll
    for (int j = 0; j < 4; j++)
        tile[ty + j * 8][tx] = red_w[(size_t)(k0 + ty + j * 8) * Cn + o0 + tx];
    __syncthreads();
    #pragma unroll
    for (int j = 0; j < 4; j++)
        g_redwT[(size_t)(o0 + ty + j * 8) * 1408 + k0 + tx] = tile[tx][ty + j * 8];
}

// ================= stageM: Y[8 batches][32 outs/block] = act(X @ W^T + b) =================
// block 256 = 8 warps; warp computes 4 output rows for 8 batches. grid (Nout/32, 4 bgroups).
template<int K, int ACT>
__global__ __launch_bounds__(256) void stageM_kernel(const float* __restrict__ X, int XS,
                                                     const float* __restrict__ W,
                                                     const float* __restrict__ bias,
                                                     float* __restrict__ Y, int YS,
                                                     const float* __restrict__ bn_g,
                                                     const float* __restrict__ bn_b,
                                                     const float* __restrict__ bn_m,
                                                     const float* __restrict__ bn_v) {
    constexpr int XQ = K / 4;
    constexpr int RED_FLOATS = 8 * 32 * 33;                 // 8448
    constexpr int SMEM_FLOATS = (8 * K > RED_FLOATS) ? 8 * K : RED_FLOATS;
    __shared__ __align__(16) float smem[SMEM_FLOATS];
    float4* Xs = (float4*)smem;
    int tid = threadIdx.x;
    int bg = blockIdx.y;
    int w = tid >> 5, l = tid & 31;

    for (int q = tid; q < 8 * XQ; q += 256) {
        int bb = q / XQ, kq = q % XQ;
        Xs[q] = *(const float4*)(X + (size_t)(bg * 8 + bb) * XS + kq * 4);
    }
    __syncthreads();

    int o0 = blockIdx.x * 32 + w * 4;
    float acc[4][8];
    #pragma unroll
    for (int u = 0; u < 4; u++)
        #pragma unroll
        for (int bb = 0; bb < 8; bb++) acc[u][bb] = 0.f;

    #pragma unroll
    for (int ki = 0; ki < K / 128; ki++) {
        int kq = ki * 32 + l;
        float4 xv[8];
        #pragma unroll
        for (int bb = 0; bb < 8; bb++) xv[bb] = Xs[bb * XQ + kq];
        float4 wv[4];
        #pragma unroll
        for (int u = 0; u < 4; u++)
            wv[u] = *(const float4*)(W + (size_t)(o0 + u) * K + kq * 4);
        #pragma unroll
        for (int u = 0; u < 4; u++)
            #pragma unroll
            for (int bb = 0; bb < 8; bb++) {
                acc[u][bb] = fmaf(wv[u].x, xv[bb].x, acc[u][bb]);
                acc[u][bb] = fmaf(wv[u].y, xv[bb].y, acc[u][bb]);
                acc[u][bb] = fmaf(wv[u].z, xv[bb].z, acc[u][bb]);
                acc[u][bb] = fmaf(wv[u].w, xv[bb].w, acc[u][bb]);
            }
    }
    __syncthreads();           // done with Xs; reuse smem as reduction scratch

    float* red = smem;         // [8 warps][32 slots][33]
    #pragma unroll
    for (int u = 0; u < 4; u++)
        #pragma unroll
        for (int bb = 0; bb < 8; bb++)
            red[(w * 32 + u * 8 + bb) * 33 + l] = acc[u][bb];
    __syncwarp();
    float s = 0.f;
    #pragma unroll
    for (int j = 0; j < 32; j++) s += red[(w * 32 + l) * 33 + j];

    int o = o0 + (l >> 3);
    int bb = l & 7;
    s += bias[o];
    if (ACT == 1) {
        s = fmaf(bn_g[o] * (s - bn_m[o]), rsqrtf(bn_v[o] + 1e-5f), bn_b[o]);
        s = (s >= 0.f) ? s : 0.2f * s;
    }
    Y[(size_t)(bg * 8 + bb) * YS + o] = s;
}

// ================= out: out[b,m,c] = base[b][c] + coarse[b,m]·red_w[1408:1411] =================
__global__ void out_kernel(const float* __restrict__ red_w,
                           const float* __restrict__ coarse, float* __restrict__ out) {
    int gid = blockIdx.x * blockDim.x + threadIdx.x;
    if (gid >= Bn * Mn * (Cn / 4)) return;
    int qd = gid % (Cn / 4);
    int bm = gid / (Cn / 4);
    int b = bm / Mn;
    int c = qd * 4;

    float4 acc = *(const float4*)(g_base + b * Cn + c);
    float c0 = coarse[bm * 3 + 0];
    float c1 = coarse[bm * 3 + 1];
    float c2 = coarse[bm * 3 + 2];
    float4 w0 = *(const float4*)(red_w + (size_t)1408 * Cn + c);
    float4 w1 = *(const float4*)(red_w + (size_t)1409 * Cn + c);
    float4 w2 = *(const float4*)(red_w + (size_t)1410 * Cn + c);
    acc.x += c0 * w0.x + c1 * w1.x + c2 * w2.x;
    acc.y += c0 * w0.y + c1 * w1.y + c2 * w2.y;
    acc.z += c0 * w0.z + c1 * w1.z + c2 * w2.z;
    acc.w += c0 * w0.w + c1 * w1.w + c2 * w2.w;
    *(float4*)(out + (size_t)bm * Cn + c) = acc;
}

// ---------------- launch ----------------
extern "C" void kernel_launch(void* const* d_in, const int* in_sizes, int n_in,
                              void* d_out, int out_size) {
    (void)in_sizes; (void)n_in; (void)out_size;
    const float* coarse     = (const float*)d_in[1];
    const float* skeleton   = (const float*)d_in[2];
    const float* gc1_wroot  = (const float*)d_in[3];
    const float* gc1_wrel   = (const float*)d_in[4];
    const float* gc1_b      = (const float*)d_in[5];
    const float* gc2_wroot  = (const float*)d_in[6];
    const float* gc2_wrel   = (const float*)d_in[7];
    const float* gc2_b      = (const float*)d_in[8];
    const float* proj_w     = (const float*)d_in[9];
    const float* proj_b     = (const float*)d_in[10];
    const float* attn_in_w  = (const float*)d_in[11];
    const float* attn_in_b  = (const float*)d_in[12];
    const float* attn_out_w = (const float*)d_in[13];
    const float* attn_out_b = (const float*)d_in[14];
    const float* inc1_w     = (const float*)d_in[15];
    const float* inc1_b     = (const float*)d_in[16];
    const float* bn_g       = (const float*)d_in[17];
    const float* bn_b       = (const float*)d_in[18];
    const float* bn_m       = (const float*)d_in[19];
    const float* bn_v       = (const float*)d_in[20];
    const float* inc2_w     = (const float*)d_in[21];
    const float* inc2_b     = (const float*)d_in[22];
    const float* red_w      = (const float*)d_in[23];
    const float* red_b      = (const float*)d_in[24];
    float* out = (float*)d_out;

    void *p_g2qc, *p_g1, *p_redwT, *p_base;
    cudaGetSymbolAddress(&p_g2qc, g_g2qc);
    cudaGetSymbolAddress(&p_g1, g_g1);
    cudaGetSymbolAddress(&p_redwT, g_redwT);
    cudaGetSymbolAddress(&p_base, g_base);
    float* f_g2qc = (float*)p_g2qc;
    float* f_g1 = (float*)p_g1;
    float* f_redwT = (float*)p_redwT;
    float* f_base = (float*)p_base;

    knn_gc1_kernel<<<dim3(Bn, 4), 512>>>(skeleton, gc1_wroot, gc1_wrel, gc1_b);
    agg_kernel<<<(NROWS * 64) / 256, 256>>>();
    gc2_kernel<<<128, 256>>>(gc2_wroot, gc2_wrel, gc2_b);
    redw_transpose_kernel<<<dim3(44, 12), 256>>>(red_w);
    chain1_kernel<<<Bn, Cn>>>(proj_w, proj_b, attn_in_w, attn_in_b, attn_out_w, attn_out_b);

    // g1 = leaky(BN(qc @ inc1^T + b1))
    stageM_kernel<384, 1><<<dim3(32, 4), 256>>>(f_g2qc + 1024, 1408, inc1_w, inc1_b,
                                                f_g1, 1024, bn_g, bn_b, bn_m, bn_v);
    // g2 = g1 @ inc2^T + b2
    stageM_kernel<1024, 0><<<dim3(32, 4), 256>>>(f_g1, 1024, inc2_w, inc2_b,
                                                 f_g2qc, 1408, nullptr, nullptr, nullptr, nullptr);
    // base = [g2, qc] @ red_w[0:1408] + red_b
    stageM_kernel<1408, 0><<<dim3(12, 4), 256>>>(f_g2qc, 1408, f_redwT, red_b,
                                                 f_base, Cn, nullptr, nullptr, nullptr, nullptr);

    out_kernel<<<(Bn * Mn * (Cn / 4) + 255) / 256, 256>>>(red_w, coarse, out);
}